// round 9
// baseline (speedup 1.0000x reference)
#include <cuda_runtime.h>
#include <math.h>

// ROC-Star pairwise loss, B=256, E=8192, C=19.
// SINGLE kernel, 32 blocks x 1024 threads, (chunk -> all classes) blocking:
//  P1: coalesced load of this chunk of all 4 epoch arrays (78KB) -> SMEM
//      staged as (tval, signed-rand); per-class positive counts via smem
//      atomics (free during load). Batch y staged similarly (sign=label).
//  X : publish per-chunk counts, arrive-counter spin (32 co-resident
//      blocks guaranteed), then each block sums caps -> p[c].
//  P2: warp w compacts class w's selected elements from SMEM (stride 19
//      is coprime to 32 banks -> conflict-free): neg-list grows from 0,
//      pos-list from 255 of the same 256-slot buffer.
//  P3: thread (grp,i) handles classes grp+4m vs batch element i; 5
//      per-class register accumulators; fixed-order reductions -> d_part.
//  P4: integer ticket; last block reduces partials + degenerate handling
//      + mean; resets counters for graph replay.

#define TPB    1024
#define MAXC   20
#define MAXCH  64
#define RPC    256          // rows per chunk

__device__ int      d_chunkcnt[MAXCH * MAXC];
__device__ float    d_part[MAXC * MAXCH];
__device__ unsigned d_arrive;   // zero-init; last block resets
__device__ unsigned d_ticket;   // zero-init; last block resets

__global__ void __launch_bounds__(TPB, 1)
rocstar_fused(const float* __restrict__ epoch_pred,
              const float* __restrict__ epoch_true,
              const float* __restrict__ rand_pos,
              const float* __restrict__ rand_neg,
              const float* __restrict__ gamma,
              const float* __restrict__ y_pred,
              const float* __restrict__ y_true,
              float* __restrict__ out,
              int Bn, int Cn, int En, int chunks)
{
    int b    = blockIdx.x;
    int t    = threadIdx.x;
    int lane = t & 31, w = t >> 5;

    extern __shared__ float sm[];
    float* s_tval = sm;                    // [MAXC*RPC]
    float* s_r    = sm + MAXC * RPC;       // [MAXC*RPC] sign = etb
    float* s_y    = sm + 2 * MAXC * RPC;   // [MAXC*RPC] sign = batch label
    float* s_list = sm + 3 * MAXC * RPC;   // [MAXC*RPC] neg from 0, pos from 255

    __shared__ float s_g[MAXC], s_p[MAXC], s_res[MAXC];
    __shared__ int   s_cnt[MAXC], s_totN[MAXC], s_totP[MAXC];
    __shared__ float s_wred[32][5];
    __shared__ unsigned s_last;

    if (t < Cn) { s_g[t] = gamma[t]; s_cnt[t] = 0; }
    __syncthreads();

    // ---- P1: coalesced chunk load + stage + count ----
    int row0 = b * RPC;
    int rows = min(RPC, En - row0);
    int nel  = rows * Cn;
    size_t base = (size_t)row0 * Cn;
    for (int idx = t; idx < nel; idx += TPB) {
        float e  = epoch_pred[base + idx];
        float et = epoch_true[base + idx];
        float rp = rand_pos [base + idx];
        float rn = rand_neg [base + idx];
        int   c  = idx % Cn;
        bool  pos = et >= 0.5f;
        float g  = s_g[c];
        s_tval[idx] = pos ? (g - e) : (e + g);
        float rr = pos ? rp : rn;
        s_r[idx] = pos ? -(rr + 1.0f) : (rr + 1.0f);
        if (pos) atomicAdd(&s_cnt[c], 1);
    }
    int nbat = min(Bn, RPC) * Cn;
    for (int idx = t; idx < nbat; idx += TPB) {
        float y   = y_pred[idx];
        bool  pos = y_true[idx] >= 0.5f;
        s_y[idx] = pos ? (y + 1.0f) : -(y + 1.0f);
    }
    __syncthreads();

    // ---- X: publish counts, arrive, spin, gather caps ----
    if (t < Cn) d_chunkcnt[b * MAXC + t] = s_cnt[t];
    __threadfence();
    __syncthreads();
    if (t == 0) {
        atomicAdd(&d_arrive, 1u);
        while (*((volatile unsigned*)&d_arrive) < (unsigned)chunks)
            __nanosleep(40);
        __threadfence();
    }
    __syncthreads();
    if (t < Cn) {
        int cap = 0;
        for (int k = 0; k < chunks; k++)
            cap += *((volatile int*)&d_chunkcnt[k * MAXC + t]);
        s_p[t] = 1000.0f / fmaxf((float)cap, 1.0f);
    }
    __syncthreads();

    // ---- P2: per-warp per-class compaction (deterministic) ----
    if (w < Cn) {
        float p = s_p[w];
        int tnN = 0, tnP = 0;
        int nrounds = (rows + 31) / 32;
        for (int rd = 0; rd < nrounds; rd++) {
            int row = rd * 32 + lane;
            bool sp = false, sn = false;
            float tv = 0.f;
            if (row < rows) {
                float rr = s_r[row * Cn + w];
                tv = s_tval[row * Cn + w];
                bool pos  = rr < 0.f;
                bool sel  = (fabsf(rr) - 1.0f) < p;
                sp = pos && sel;
                sn = (!pos) && sel;
            }
            unsigned bp = __ballot_sync(0xffffffffu, sp);
            unsigned bn = __ballot_sync(0xffffffffu, sn);
            unsigned lm = (1u << lane) - 1u;
            if (sn) s_list[w * RPC + tnN + __popc(bn & lm)] = tv;
            if (sp) s_list[w * RPC + (RPC - 1) - (tnP + __popc(bp & lm))] = tv;
            tnN += __popc(bn);
            tnP += __popc(bp);
        }
        if (lane == 0) { s_totN[w] = tnN; s_totP[w] = tnP; }
    }
    __syncthreads();

    // ---- P3: pairwise. thread -> (grp = t>>8, i = t&255); class grp+4m ----
    float acc[5];
    int grp = t >> 8;          // 0..3
    int i   = t & 255;
    #pragma unroll
    for (int m = 0; m < 5; m++) {
        acc[m] = 0.f;
        int cc = grp + 4 * m;
        if (cc < Cn) {
            float ap = 1e30f, an = 1e30f;
            if (i < Bn) {
                float ys = s_y[i * Cn + cc];
                float y  = fabsf(ys) - 1.0f;
                if (ys > 0.f) ap = y;
                else          an = -y;
            }
            int tn = s_totN[cc], tp = s_totP[cc];
            const float* ln = &s_list[cc * RPC];
            float a = 0.f;
            for (int k = 0; k < tn; k++) {          // epoch negs vs batch pos
                float d = ln[k] - ap;               // e + g - y
                float r2 = fmaxf(d, 0.f);
                a = fmaf(r2, r2, a);
            }
            for (int k = 0; k < tp; k++) {          // epoch pos vs batch negs
                float d = ln[(RPC - 1) - k] - an;   // y - e + g
                float r2 = fmaxf(d, 0.f);
                a = fmaf(r2, r2, a);
            }
            acc[m] = a;
        }
    }
    // fixed-order reduce: warp shuffles, then per-class sum of 8 warp cells
    #pragma unroll
    for (int m = 0; m < 5; m++) {
        float a = acc[m];
        #pragma unroll
        for (int o = 16; o > 0; o >>= 1)
            a += __shfl_down_sync(0xffffffffu, a, o);
        if (lane == 0) s_wred[w][m] = a;
    }
    __syncthreads();
    if (t < Cn) {
        int cc = t, g2 = cc & 3, m2 = cc >> 2;
        float s = 0.f;
        #pragma unroll
        for (int k = 0; k < 8; k++) s += s_wred[g2 * 8 + k][m2];
        d_part[cc * MAXCH + b] = s;
    }
    __threadfence();
    __syncthreads();

    // ---- P4: ticket; last block finalizes ----
    if (t == 0)
        s_last = (atomicAdd(&d_ticket, 1u) == (unsigned)(chunks - 1)) ? 1u : 0u;
    __syncthreads();
    if (!s_last) return;
    __threadfence();

    if (w < Cn) {
        float m = 0.f;
        for (int k = lane; k < chunks; k += 32)
            m += *((volatile float*)&d_part[w * MAXCH + k]);
        float sy = 0.f;
        int   np = 0;
        for (int i2 = lane; i2 < Bn; i2 += 32) {
            float y = y_pred[i2 * Cn + w];
            sy += y;
            np += (y_true[i2 * Cn + w] >= 0.5f) ? 1 : 0;
        }
        #pragma unroll
        for (int o = 16; o > 0; o >>= 1) {
            m  += __shfl_down_sync(0xffffffffu, m,  o);
            sy += __shfl_down_sync(0xffffffffu, sy, o);
            np += __shfl_down_sync(0xffffffffu, np, o);
        }
        if (lane == 0) {
            float res = m / 1000.0f;             // m2/MAX_POS + m3/MAX_NEG
            if (isnan(res)) res = 0.f;
            if (np == 0 || np == Bn) res = sy * 1e-8f;
            s_res[w] = res;
        }
    }
    __syncthreads();
    if (w == 0) {
        float r = (lane < Cn) ? s_res[lane] : 0.f;
        #pragma unroll
        for (int o = 16; o > 0; o >>= 1)
            r += __shfl_down_sync(0xffffffffu, r, o);
        if (lane == 0) {
            out[0]   = r / (float)Cn;
            d_arrive = 0;                        // reset for graph replay
            d_ticket = 0;
        }
    }
}

extern "C" void kernel_launch(void* const* d_in, const int* in_sizes, int n_in,
                              void* d_out, int out_size)
{
    const float* y_pred     = (const float*)d_in[0];
    const float* y_true     = (const float*)d_in[1];
    const float* epoch_pred = (const float*)d_in[2];
    const float* epoch_true = (const float*)d_in[3];
    const float* gamma      = (const float*)d_in[4];
    const float* rand_pos   = (const float*)d_in[5];
    const float* rand_neg   = (const float*)d_in[6];

    int Cn = in_sizes[4];            // gamma: [C]
    int Bn = in_sizes[0] / Cn;       // y_pred: [B, C]
    int En = in_sizes[2] / Cn;       // epoch_pred: [E, C]
    int chunks = (En + RPC - 1) / RPC;

    size_t smem = (size_t)4 * MAXC * RPC * sizeof(float);   // 80 KB
    cudaFuncSetAttribute(rocstar_fused,
                         cudaFuncAttributeMaxDynamicSharedMemorySize,
                         (int)smem);

    rocstar_fused<<<chunks, TPB, smem>>>(epoch_pred, epoch_true, rand_pos,
                                         rand_neg, gamma, y_pred, y_true,
                                         (float*)d_out, Bn, Cn, En, chunks);
}

// round 11
// speedup vs baseline: 1.2576x; 1.2576x over previous
#include <cuda_runtime.h>
#include <math.h>

// ROC-Star pairwise loss, B=256, E=8192, C=19.
// Kernel A: coalesced read of all epoch arrays once -> SMEM transpose ->
//           class-major staging tvalT/rT (+ per-chunk positive counts,
//           plain stores). One extra block: batch transpose + npos/sumyp.
// Kernel B: (chunk, class) blocks read STAGED class-major data (3 coalesced
//           loads/thread), derive cap from chunk counts, ballot-compact,
//           pairwise relu^2, fixed-order reduce; integer-ticket last block
//           finalizes (degenerate handling + mean) and resets the ticket.

#define TPB     256
#define MAXC    20
#define MAXE    8192
#define ROWS_A  128                    // rows per transpose block
#define MAXCHA  (MAXE / ROWS_A)        // 64
#define MAXCHB  (MAXE / TPB)           // 32
#define SBUF    (TPB * MAXC)           // 5120 floats: fits epoch AND batch use

__device__ float    d_tvalT[MAXC * MAXE];     // class-major staged tval
__device__ float    d_rT[MAXC * MAXE];        // class-major rand, sign=etb
__device__ float    d_ysT[MAXC * TPB];        // class-major batch y, sign=label
__device__ int      d_chunkcnt[MAXC * MAXCHA];
__device__ int      d_npos[MAXC];
__device__ float    d_sumyp[MAXC];
__device__ float    d_part[MAXC * MAXCHB];
__device__ unsigned d_ticket;                 // zero-init; last block resets

__global__ void __launch_bounds__(TPB)
stage_kernel(const float* __restrict__ epoch_pred,
             const float* __restrict__ epoch_true,
             const float* __restrict__ rand_pos,
             const float* __restrict__ rand_neg,
             const float* __restrict__ gamma,
             const float* __restrict__ y_pred,
             const float* __restrict__ y_true,
             int Bn, int Cn, int En, int chunksA)
{
    __shared__ float s_a[SBUF];            // tval (epoch) / signed y (batch)
    __shared__ float s_b[SBUF];            // signed rand (epoch only)
    __shared__ float s_gm[MAXC];
    __shared__ int   s_cnt[MAXC];
    int t = threadIdx.x;
    int b = blockIdx.x;

    if (b < chunksA) {
        // ---- epoch transpose block: rows [r0, r0+nr) of all classes ----
        if (t < Cn) { s_gm[t] = gamma[t]; s_cnt[t] = 0; }
        __syncthreads();
        int r0 = b * ROWS_A;
        int nr = min(ROWS_A, En - r0);
        int nel = nr * Cn;                 // <= 128*19 = 2432 < SBUF
        size_t base = (size_t)r0 * Cn;
        for (int idx = t; idx < nel; idx += TPB) {
            float e  = epoch_pred[base + idx];
            float et = epoch_true[base + idx];
            float rp = rand_pos [base + idx];
            float rn = rand_neg [base + idx];
            int   c  = idx % Cn;
            bool pos = et >= 0.5f;
            float g  = s_gm[c];
            s_a[idx] = pos ? (g - e) : (e + g);
            s_b[idx] = pos ? -(rp + 1.0f) : (rn + 1.0f);
            if (pos) atomicAdd(&s_cnt[c], 1);
        }
        __syncthreads();
        // class-major writes, coalesced in nr-long runs
        // (smem reads stride Cn=19, coprime to 32 banks: conflict-free)
        for (int o = t; o < nel; o += TPB) {
            int c  = o / nr;
            int rl = o - c * nr;
            d_tvalT[c * En + r0 + rl] = s_a[rl * Cn + c];
            d_rT   [c * En + r0 + rl] = s_b[rl * Cn + c];
        }
        if (t < Cn)
            d_chunkcnt[t * MAXCHA + b] = s_cnt[t];   // plain store: replay-safe
    } else {
        // ---- batch block: transpose signed y + per-class npos/sumyp ----
        int nel = Bn * Cn;                 // 256*19 = 4864 <= SBUF
        for (int idx = t; idx < nel; idx += TPB) {
            float yp = y_pred[idx];
            bool pos = y_true[idx] >= 0.5f;
            s_a[idx] = pos ? (yp + 1.0f) : -(yp + 1.0f);
        }
        __syncthreads();
        for (int o = t; o < nel; o += TPB) {
            int c = o / Bn;
            int i = o - c * Bn;
            d_ysT[c * TPB + i] = s_a[i * Cn + c];
        }
        int lane = t & 31, w = t >> 5;
        for (int c = w; c < Cn; c += 8) {
            float sy = 0.f; int np = 0;
            for (int i = lane; i < Bn; i += 32) {
                float v = s_a[i * Cn + c];
                sy += fabsf(v) - 1.0f;
                np += (v > 0.f) ? 1 : 0;
            }
            #pragma unroll
            for (int o = 16; o > 0; o >>= 1) {
                sy += __shfl_down_sync(0xffffffffu, sy, o);
                np += __shfl_down_sync(0xffffffffu, np, o);
            }
            if (lane == 0) { d_sumyp[c] = sy; d_npos[c] = np; }
        }
    }
}

__global__ void __launch_bounds__(TPB)
loss_kernel(float* __restrict__ out,
            int Bn, int Cn, int En, int chunksA, int chunksB)
{
    int c    = blockIdx.y;
    int tid  = threadIdx.x;
    int lane = tid & 31, w = tid >> 5;
    int j    = blockIdx.x * TPB + tid;

    // ---- 3 coalesced loads ----
    float tv = 0.f, rv = 1e30f;            // padding never selected
    if (j < En) {
        tv = d_tvalT[c * En + j];
        rv = d_rT   [c * En + j];
    }
    float ys = (tid < Bn) ? d_ysT[c * TPB + tid] : 0.f;

    // ---- cap: chunksA counts (2 L2 sectors), fixed-order reduce ----
    __shared__ int s_capw[2];
    int v = (tid < chunksA) ? d_chunkcnt[c * MAXCHA + tid] : 0;
    if (w < 2) {
        #pragma unroll
        for (int o = 16; o > 0; o >>= 1)
            v += __shfl_down_sync(0xffffffffu, v, o);
        if (lane == 0) s_capw[w] = v;
    }
    __syncthreads();
    float p = 1000.0f / fmaxf((float)(s_capw[0] + s_capw[1]), 1.0f);

    bool ispos  = rv < 0.f;
    bool sel    = (fabsf(rv) - 1.0f) < p;
    bool selpos = ispos && sel;
    bool selneg = (!ispos) && sel;

    // ---- deterministic ballot compaction ----
    __shared__ float s_tn[TPB], s_tp[TPB];
    __shared__ int wcN[8], wcP[8];
    unsigned bn = __ballot_sync(0xffffffffu, selneg);
    unsigned bp = __ballot_sync(0xffffffffu, selpos);
    if (lane == 0) { wcN[w] = __popc(bn); wcP[w] = __popc(bp); }
    __syncthreads();
    int offN = 0, offP = 0, totN = 0, totP = 0;
    #pragma unroll
    for (int k = 0; k < 8; k++) {
        int vn = wcN[k], vp = wcP[k];
        if (k < w) { offN += vn; offP += vp; }
        totN += vn; totP += vp;
    }
    unsigned lmask = (1u << lane) - 1u;
    if (selneg) s_tn[offN + __popc(bn & lmask)] = tv;
    if (selpos) s_tp[offP + __popc(bp & lmask)] = tv;
    __syncthreads();

    // ---- pairwise: thread owns batch element tid ----
    float apos = 1e30f, aneg = 1e30f;
    if (tid < Bn) {
        float y = fabsf(ys) - 1.0f;
        if (ys > 0.f) apos = y;
        else          aneg = -y;
    }
    float acc = 0.f;
    #pragma unroll 4
    for (int k = 0; k < totN; k++) {
        float d = s_tn[k] - apos;        // e + g - y
        float r = fmaxf(d, 0.f);
        acc = fmaf(r, r, acc);
    }
    #pragma unroll 4
    for (int k = 0; k < totP; k++) {
        float d = s_tp[k] - aneg;        // y - e + g
        float r = fmaxf(d, 0.f);
        acc = fmaf(r, r, acc);
    }

    // ---- fixed-order block reduce ----
    #pragma unroll
    for (int o = 16; o > 0; o >>= 1)
        acc += __shfl_down_sync(0xffffffffu, acc, o);
    __shared__ float wsum[8];
    if (lane == 0) wsum[w] = acc;
    __syncthreads();
    if (tid == 0) {
        float s = 0.f;
        #pragma unroll
        for (int k = 0; k < 8; k++) s += wsum[k];
        d_part[c * MAXCHB + blockIdx.x] = s;
    }

    // ---- integer-ticket last-block finalize ----
    __threadfence();
    __shared__ unsigned s_last;
    if (tid == 0) {
        unsigned total = gridDim.x * gridDim.y;
        s_last = (atomicAdd(&d_ticket, 1u) == total - 1u) ? 1u : 0u;
    }
    __syncthreads();
    if (!s_last) return;
    __threadfence();

    __shared__ float sres[MAXC];
    for (int cc = w; cc < Cn; cc += 8) {
        float m = 0.f;
        for (int k = lane; k < chunksB; k += 32)
            m += *((volatile float*)&d_part[cc * MAXCHB + k]);
        #pragma unroll
        for (int o = 16; o > 0; o >>= 1)
            m += __shfl_down_sync(0xffffffffu, m, o);
        if (lane == 0) {
            float res = m / 1000.0f;              // m2/MAX_POS + m3/MAX_NEG
            if (isnan(res)) res = 0.f;
            int np = d_npos[cc];
            if (np == 0 || np == Bn) res = d_sumyp[cc] * 1e-8f;
            sres[cc] = res;
        }
    }
    __syncthreads();
    if (w == 0) {
        float r = (lane < Cn) ? sres[lane] : 0.f;
        #pragma unroll
        for (int o = 16; o > 0; o >>= 1)
            r += __shfl_down_sync(0xffffffffu, r, o);
        if (lane == 0) {
            out[0]   = r / (float)Cn;
            d_ticket = 0;                         // reset for graph replay
        }
    }
}

extern "C" void kernel_launch(void* const* d_in, const int* in_sizes, int n_in,
                              void* d_out, int out_size)
{
    const float* y_pred     = (const float*)d_in[0];
    const float* y_true     = (const float*)d_in[1];
    const float* epoch_pred = (const float*)d_in[2];
    const float* epoch_true = (const float*)d_in[3];
    const float* gamma      = (const float*)d_in[4];
    const float* rand_pos   = (const float*)d_in[5];
    const float* rand_neg   = (const float*)d_in[6];

    int Cn = in_sizes[4];            // gamma: [C]
    int Bn = in_sizes[0] / Cn;       // y_pred: [B, C]
    int En = in_sizes[2] / Cn;       // epoch_pred: [E, C]
    int chunksA = (En + ROWS_A - 1) / ROWS_A;
    int chunksB = (En + TPB - 1) / TPB;

    stage_kernel<<<chunksA + 1, TPB>>>(epoch_pred, epoch_true, rand_pos,
                                       rand_neg, gamma, y_pred, y_true,
                                       Bn, Cn, En, chunksA);
    dim3 grid(chunksB, Cn);
    loss_kernel<<<grid, TPB>>>((float*)d_out, Bn, Cn, En, chunksA, chunksB);
}